// round 7
// baseline (speedup 1.0000x reference)
#include <cuda_runtime.h>
#include <math.h>
#include <stdint.h>

// ---------------- problem constants ----------------
#define BATCH 4
#define NPIX  65536      // 256*256
#define LHW   64
#define CLAT  32

// per-batch scratch (floats). Weight tiles stored transposed [n][kpad] with
// pair-permuted + block-XOR layout:
//   idx(n,k) = n*kpad + ((k&~7) ^ (8*(n&3))) + 2*(k&3) + ((k>>2)&1)
#define OFFB0    0       // 128 x 64   (8192 floats, K 40 padded to 64, zero-filled)
#define OFFB1    8192    // 128 x 128  (16384)
#define OFFB2    24576
#define OFFB3    40960
#define OFF_BIAS 57344   // 4 * 128 bias rows (fp32)
#define OFF_W4   57856   // 129*2 normalized W4 (pi-permuted k) + bias row
#define WSTRIDE  58368

__device__ __align__(16) float g_wmod[BATCH * WSTRIDE];

// ================= PTX helpers (sm_100-baseline safe) =================
#define MBARRIER_INIT(mb, cnt) \
    asm volatile("mbarrier.init.shared.b64 [%0], %1;" :: "r"((uint32_t)(mb)), "r"((uint32_t)(cnt)) : "memory")
#define MBARRIER_ARRIVE(mb) \
    asm volatile("mbarrier.arrive.shared.b64 _, [%0];" :: "r"((uint32_t)(mb)) : "memory")
#define MBARRIER_EXPECT_TX(mb, bytes) \
    asm volatile("mbarrier.arrive.expect_tx.shared.b64 _, [%0], %1;" \
                 :: "r"((uint32_t)(mb)), "r"((uint32_t)(bytes)) : "memory")
#define MBARRIER_WAIT_PARITY(mb, par) do { \
    uint32_t _mb = (uint32_t)(mb), _p = (uint32_t)(par), _done; \
    asm volatile("{\n\t.reg .pred p;\n\t" \
        "mbarrier.try_wait.parity.acquire.cta.shared::cta.b64 p, [%1], %2;\n\t" \
        "selp.b32 %0, 1, 0, p;\n\t}" : "=r"(_done) : "r"(_mb), "r"(_p) : "memory"); \
    if (!_done) { \
        asm volatile("{\n\t.reg .pred P1;\n\t" \
            "WL_%=:\n\t" \
            "mbarrier.try_wait.parity.acquire.cta.shared::cta.b64 P1, [%0], %1, 0x989680;\n\t" \
            "@P1 bra.uni WD_%=;\n\t" \
            "bra.uni WL_%=;\n\t" \
            "WD_%=:\n\t}" :: "r"(_mb), "r"(_p) : "memory"); \
    } \
} while (0)
#define BULK_G2S(dst, src, bytes, mb) \
    asm volatile("cp.async.bulk.shared::cluster.global.mbarrier::complete_tx::bytes [%0], [%1], %2, [%3];" \
                 :: "r"((uint32_t)(dst)), "l"(src), "r"((uint32_t)(bytes)), "r"((uint32_t)(mb)) : "memory")
#define BAR_SYNC(id, cnt) \
    asm volatile("bar.sync %0, %1;" :: "r"(id), "r"(cnt) : "memory")

__device__ __forceinline__ uint32_t smem_to_u32(const void* p) {
    uint32_t a;
    asm("{ .reg .u64 t; cvta.to.shared.u64 t, %1; cvt.u32.u64 %0, t; }" : "=r"(a) : "l"(p));
    return a;
}
__device__ __forceinline__ uint32_t f2tf32(float x) {
    uint32_t u;
    asm("cvt.rna.tf32.f32 %0, %1;" : "=r"(u) : "f"(x));
    return u;
}
// pair-permutation within 8-blocks: (k, k+4) -> adjacent
__device__ __forceinline__ int pi_k(int k) {
    return (k & ~7) + 2 * (k & 3) + ((k >> 2) & 1);
}

// ---------------- kernel A: modulate + normalize + pack ----------------
__global__ void modulate_kernel(
    const float* __restrict__ w0, const float* __restrict__ w1,
    const float* __restrict__ w2, const float* __restrict__ w3,
    const float* __restrict__ w4,
    const float* __restrict__ m0, const float* __restrict__ m1,
    const float* __restrict__ m2, const float* __restrict__ m3,
    const float* __restrict__ m4)
{
    int gw   = (blockIdx.x * blockDim.x + threadIdx.x) >> 5;
    int lane = threadIdx.x & 31;
    if (gw >= BATCH * 514) return;
    int b = gw / 514;
    int r = gw % 514;
    int layer, o;
    if (r < 512) { layer = r >> 7; o = r & 127; }
    else         { layer = 4;      o = r - 512; }

    float* g = g_wmod + (size_t)b * WSTRIDE;

    if (layer < 4) {
        const float* w; const float* m; int fr, off, kpad;
        switch (layer) {
          case 0:  w = w0; m = m0; fr = 35;  off = OFFB0; kpad = 64;  break;
          case 1:  w = w1; m = m1; fr = 128; off = OFFB1; kpad = 128; break;
          case 2:  w = w2; m = m2; fr = 128; off = OFFB2; kpad = 128; break;
          default: w = w3; m = m3; fr = 128; off = OFFB3; kpad = 128; break;
        }
        float ss = 0.f;
        for (int k = lane; k < fr; k += 32) {
            float v = w[k * 128 + o] * m[((size_t)b * fr + k) * 128 + o];
            ss += v * v;
        }
        #pragma unroll
        for (int s = 16; s; s >>= 1) ss += __shfl_xor_sync(0xffffffffu, ss, s);
        float inv = 1.f / fmaxf(sqrtf(ss), 1e-12f);
        int bx = 8 * (o & 3);
        for (int k = lane; k < kpad; k += 32) {
            float v = 0.f;
            if (k < fr) v = w[k * 128 + o] * m[((size_t)b * fr + k) * 128 + o] * inv;
            int idx = ((k & ~7) ^ bx) + 2 * (k & 3) + ((k >> 2) & 1);
            g[off + o * kpad + idx] = __uint_as_float(f2tf32(v));
        }
        if (lane == 0) g[OFF_BIAS + layer * 128 + o] = w[fr * 128 + o];
    } else {
        float ss = 0.f;
        for (int k = lane; k < 128; k += 32) {
            float v = w4[k * 2 + o] * m4[((size_t)b * 128 + k) * 2 + o];
            ss += v * v;
        }
        #pragma unroll
        for (int s = 16; s; s >>= 1) ss += __shfl_xor_sync(0xffffffffu, ss, s);
        float inv = 1.f / fmaxf(sqrtf(ss), 1e-12f);
        for (int k = lane; k < 128; k += 32)
            g[OFF_W4 + pi_k(k) * 2 + o] = w4[k * 2 + o] * m4[((size_t)b * 128 + k) * 2 + o] * inv;
        if (lane == 0) g[OFF_W4 + 256 + o] = w4[128 * 2 + o];
    }
}

// ---------------- kernel B: tf32 mma.sync MLP ----------------
// CTA = 128 pixels, 256 threads; warp grid 2m x 4n (warp tile 64 x 32).
#define AP 136           // padded A row stride (floats); 136 % 32 == 8
#define MB_WF0   0
#define MB_WF1   8
#define MB_WREL  16
#define BIAS_F   16      // float idx (byte 64), 512 floats
#define W4_F     528     // 258 floats
#define A_B      4096    // 128*136*4 = 69632
#define WBUF0_B  73728
#define WBUF1_B  139264
#define SMEM_BYTES 204800

template<int KSTEPS, int KP>
__device__ __forceinline__ void mma_compute(
    const uint32_t* __restrict__ Asm, const uint32_t* __restrict__ Wsm,
    int mbase, int nbase, int lr, int lc, float acc[4][4][4])
{
    const int bx = 8 * (lr & 3);
    #pragma unroll
    for (int ks = 0; ks < KSTEPS; ks++) {
        const int kb = ks * 8;
        uint32_t a[4][4];
        #pragma unroll
        for (int mt = 0; mt < 4; mt++) {
            const uint32_t* arow = Asm + (mbase + mt * 16 + lr) * AP + kb + 2 * lc;
            uint2 a02 = *(const uint2*)arow;            // k = kb+lc, kb+lc+4
            uint2 a13 = *(const uint2*)(arow + 8 * AP); // row+8
            a[mt][0] = a02.x; a[mt][1] = a13.x; a[mt][2] = a02.y; a[mt][3] = a13.y;
        }
        #pragma unroll
        for (int q = 0; q < 4; q++) {
            uint2 bv = *(const uint2*)(Wsm + (nbase + q * 8 + lr) * KP + (kb ^ bx) + 2 * lc);
            #pragma unroll
            for (int mt = 0; mt < 4; mt++) {
                asm volatile(
                    "mma.sync.aligned.m16n8k8.row.col.f32.tf32.tf32.f32 "
                    "{%0,%1,%2,%3}, {%4,%5,%6,%7}, {%8,%9}, {%0,%1,%2,%3};"
                    : "+f"(acc[mt][q][0]), "+f"(acc[mt][q][1]),
                      "+f"(acc[mt][q][2]), "+f"(acc[mt][q][3])
                    : "r"(a[mt][0]), "r"(a[mt][1]), "r"(a[mt][2]), "r"(a[mt][3]),
                      "r"(bv.x), "r"(bv.y));
            }
        }
    }
}

__global__ __launch_bounds__(256)
void hyponet_kernel(const float* __restrict__ coord,
                    const float* __restrict__ lat,
                    float* __restrict__ out)
{
    extern __shared__ __align__(1024) char smem[];
    float*    smf = (float*)smem;
    uint32_t* Au  = (uint32_t*)(smem + A_B);
    float*    Af  = (float*)(smem + A_B);
    const uint32_t sb  = smem_to_u32(smem);
    const uint32_t wf0 = sb + MB_WF0, wf1 = sb + MB_WF1, wrel = sb + MB_WREL;

    const int tid  = threadIdx.x;
    const int warp = tid >> 5, lane = tid & 31;
    const int lr = lane >> 2, lc = lane & 3;
    const int mgrp  = warp & 1;
    const int mbase = mgrp * 64;
    const int nbase = (warp >> 1) * 32;
    const int b     = blockIdx.x >> 9;
    const int pbase = (blockIdx.x & 511) << 7;
    const float* gw = g_wmod + (size_t)b * WSTRIDE;

    if (tid == 0) {
        MBARRIER_INIT(wf0, 1);
        MBARRIER_INIT(wf1, 1);
        MBARRIER_INIT(wrel, 8);
    }
    __syncthreads();
    if (tid == 0) {
        MBARRIER_EXPECT_TX(wf0, 32768);
        BULK_G2S(sb + WBUF0_B, gw + OFFB0, 32768, wf0);
        MBARRIER_EXPECT_TX(wf1, 65536);
        BULK_G2S(sb + WBUF1_B, gw + OFFB1, 65536, wf1);
    }

    // ---- prologue: bilinear latent + coord -> A tile (pi-permuted k) ----
    if (tid < 128) {
        int p = tid, n = pbase + p;
        int y = n >> 8, x = n & 255;
        const float* c = coord + ((size_t)b * NPIX + n) * 3;
        float sy = (y + 0.5f) * 0.25f - 0.5f;
        float sx = (x + 0.5f) * 0.25f - 0.5f;
        float fy0 = floorf(sy), fx0 = floorf(sx);
        float fy = sy - fy0,    fx = sx - fx0;
        int y0 = max(0, min(LHW - 1, (int)fy0));
        int y1 = max(0, min(LHW - 1, (int)fy0 + 1));
        int x0 = max(0, min(LHW - 1, (int)fx0));
        int x1 = max(0, min(LHW - 1, (int)fx0 + 1));
        float w00 = (1.f - fy) * (1.f - fx), w01 = (1.f - fy) * fx;
        float w10 = fy * (1.f - fx),         w11 = fy * fx;
        const float* base = lat + (size_t)b * LHW * LHW * CLAT;
        const float4* q00 = (const float4*)(base + (y0 * LHW + x0) * CLAT);
        const float4* q01 = (const float4*)(base + (y0 * LHW + x1) * CLAT);
        const float4* q10 = (const float4*)(base + (y1 * LHW + x0) * CLAT);
        const float4* q11 = (const float4*)(base + (y1 * LHW + x1) * CLAT);
        uint32_t* arow = Au + p * AP;
        #pragma unroll
        for (int k = 0; k < 8; k++) {
            float4 a = q00[k], bb = q01[k], cc = q10[k], dd = q11[k];
            arow[pi_k(4 * k + 0)] = f2tf32(w00 * a.x + w01 * bb.x + w10 * cc.x + w11 * dd.x);
            arow[pi_k(4 * k + 1)] = f2tf32(w00 * a.y + w01 * bb.y + w10 * cc.y + w11 * dd.y);
            arow[pi_k(4 * k + 2)] = f2tf32(w00 * a.z + w01 * bb.z + w10 * cc.z + w11 * dd.z);
            arow[pi_k(4 * k + 3)] = f2tf32(w00 * a.w + w01 * bb.w + w10 * cc.w + w11 * dd.w);
        }
        arow[pi_k(32)] = f2tf32(c[0]);
        arow[pi_k(33)] = f2tf32(c[1]);
        arow[pi_k(34)] = f2tf32(c[2]);
        arow[pi_k(35)] = 0; arow[pi_k(36)] = 0; arow[pi_k(37)] = 0;
        arow[pi_k(38)] = 0; arow[pi_k(39)] = 0;
    } else {
        for (int i = tid - 128; i < 770; i += 128) smf[BIAS_F + i] = gw[OFF_BIAS + i];
    }
    __syncthreads();

    const int copy_off[2] = {OFFB2, OFFB3};
    const int barid = 1 + mgrp;
    const int p0 = (lc & 1) * 4 + (lc >> 1);   // pi position of col0=...+2*lc within 8-block

    #define LAYER_PASS(L, KS, KPV, WOFF_B, WFBAR) do { \
        MBARRIER_WAIT_PARITY(WFBAR, (L) >> 1); \
        float acc[4][4][4] = {}; \
        mma_compute<KS, KPV>(Au, (const uint32_t*)(smem + (WOFF_B)), mbase, nbase, lr, lc, acc); \
        if (lane == 0) MBARRIER_ARRIVE(wrel); \
        if (tid == 0 && (L) < 2) { \
            MBARRIER_WAIT_PARITY(wrel, (L) & 1); \
            MBARRIER_EXPECT_TX(WFBAR, 65536); \
            BULK_G2S(sb + (WOFF_B), gw + copy_off[L], 65536, WFBAR); \
        } \
        BAR_SYNC(barid, 128); \
        const float* biasL = smf + BIAS_F + (L) * 128; \
        _Pragma("unroll") \
        for (int mt = 0; mt < 4; mt++) { \
            _Pragma("unroll") \
            for (int q = 0; q < 4; q++) { \
                int blk = nbase + q * 8; \
                float2 bv = *(const float2*)(biasL + blk + 2 * lc); \
                int r0 = mbase + mt * 16 + lr; \
                Au[r0 * AP + blk + p0]           = f2tf32(__sinf(acc[mt][q][0] + bv.x)); \
                Au[r0 * AP + blk + p0 + 2]       = f2tf32(__sinf(acc[mt][q][1] + bv.y)); \
                Au[(r0 + 8) * AP + blk + p0]     = f2tf32(__sinf(acc[mt][q][2] + bv.x)); \
                Au[(r0 + 8) * AP + blk + p0 + 2] = f2tf32(__sinf(acc[mt][q][3] + bv.y)); \
            } \
        } \
        BAR_SYNC(barid, 128); \
    } while (0)

    LAYER_PASS(0, 5, 64, WBUF0_B, wf0);
    LAYER_PASS(1, 16, 128, WBUF1_B, wf1);
    LAYER_PASS(2, 16, 128, WBUF0_B, wf0);
    LAYER_PASS(3, 16, 128, WBUF1_B, wf1);
    #undef LAYER_PASS

    __syncthreads();   // both m-groups done writing A before cross-group read

    // ---- final: 128 -> 2 dot + 0.5 (fp32; W4 stored in matching pi order) ----
    {
        const float* w4 = smf + W4_F;
        int o = tid >> 7, p = tid & 127;
        float acc = w4[256 + o];
        const float* arow = Af + p * AP;
        #pragma unroll 8
        for (int k = 0; k < 128; k += 4) {
            float4 a = *(const float4*)(arow + k);
            acc += a.x * w4[(k + 0) * 2 + o];
            acc += a.y * w4[(k + 1) * 2 + o];
            acc += a.z * w4[(k + 2) * 2 + o];
            acc += a.w * w4[(k + 3) * 2 + o];
        }
        out[((size_t)b * NPIX + pbase + p) * 2 + o] = acc + 0.5f;
    }
}

// ---------------- launch ----------------
extern "C" void kernel_launch(void* const* d_in, const int* in_sizes, int n_in,
                              void* d_out, int out_size)
{
    const float* coord = (const float*)d_in[0];
    const float* lat   = (const float*)d_in[1];

    modulate_kernel<<<(2056 * 32 + 255) / 256, 256>>>(
        (const float*)d_in[2], (const float*)d_in[3], (const float*)d_in[4],
        (const float*)d_in[5], (const float*)d_in[6],
        (const float*)d_in[7], (const float*)d_in[8], (const float*)d_in[9],
        (const float*)d_in[10], (const float*)d_in[11]);

    cudaFuncSetAttribute(hyponet_kernel,
                         cudaFuncAttributeMaxDynamicSharedMemorySize, SMEM_BYTES);
    hyponet_kernel<<<BATCH * (NPIX / 128), 256, SMEM_BYTES>>>(coord, lat, (float*)d_out);
}

// round 8
// speedup vs baseline: 1.0400x; 1.0400x over previous
#include <cuda_runtime.h>
#include <math.h>
#include <stdint.h>

// ---------------- problem constants ----------------
#define BATCH 4
#define NPIX  65536      // 256*256
#define LHW   64
#define CLAT  32

// per-batch scratch (floats). Weight tiles transposed [n][kpad],
// XOR-swizzled: element (n,k) at n*kpad + (k ^ (4*(n&7))).  (R6 layout)
#define OFFB0    0       // 128 x 64   (8192 floats, K 40 padded to 64, zero-filled)
#define OFFB1    8192    // 128 x 128  (16384)
#define OFFB2    24576
#define OFFB3    40960
#define OFF_BIAS 57344   // 4 * 128 bias rows (fp32)
#define OFF_W4   57856   // 129*2 normalized W4 + bias row (fp32)
#define WSTRIDE  58368

__device__ __align__(16) float g_wmod[BATCH * WSTRIDE];

// ================= PTX helpers (sm_100-baseline safe) =================
#define MBARRIER_INIT(mb, cnt) \
    asm volatile("mbarrier.init.shared.b64 [%0], %1;" :: "r"((uint32_t)(mb)), "r"((uint32_t)(cnt)) : "memory")
#define MBARRIER_ARRIVE(mb) \
    asm volatile("mbarrier.arrive.shared.b64 _, [%0];" :: "r"((uint32_t)(mb)) : "memory")
#define MBARRIER_EXPECT_TX(mb, bytes) \
    asm volatile("mbarrier.arrive.expect_tx.shared.b64 _, [%0], %1;" \
                 :: "r"((uint32_t)(mb)), "r"((uint32_t)(bytes)) : "memory")
#define MBARRIER_WAIT_PARITY(mb, par) do { \
    uint32_t _mb = (uint32_t)(mb), _p = (uint32_t)(par), _done; \
    asm volatile("{\n\t.reg .pred p;\n\t" \
        "mbarrier.try_wait.parity.acquire.cta.shared::cta.b64 p, [%1], %2;\n\t" \
        "selp.b32 %0, 1, 0, p;\n\t}" : "=r"(_done) : "r"(_mb), "r"(_p) : "memory"); \
    if (!_done) { \
        asm volatile("{\n\t.reg .pred P1;\n\t" \
            "WL_%=:\n\t" \
            "mbarrier.try_wait.parity.acquire.cta.shared::cta.b64 P1, [%0], %1, 0x989680;\n\t" \
            "@P1 bra.uni WD_%=;\n\t" \
            "bra.uni WL_%=;\n\t" \
            "WD_%=:\n\t}" :: "r"(_mb), "r"(_p) : "memory"); \
    } \
} while (0)
#define BULK_G2S(dst, src, bytes, mb) \
    asm volatile("cp.async.bulk.shared::cluster.global.mbarrier::complete_tx::bytes [%0], [%1], %2, [%3];" \
                 :: "r"((uint32_t)(dst)), "l"(src), "r"((uint32_t)(bytes)), "r"((uint32_t)(mb)) : "memory")

__device__ __forceinline__ uint32_t smem_to_u32(const void* p) {
    uint32_t a;
    asm("{ .reg .u64 t; cvta.to.shared.u64 t, %1; cvt.u32.u64 %0, t; }" : "=r"(a) : "l"(p));
    return a;
}
__device__ __forceinline__ uint32_t f2tf32(float x) {
    uint32_t u;
    asm("cvt.rna.tf32.f32 %0, %1;" : "=r"(u) : "f"(x));
    return u;
}

// ---------------- kernel A: modulate + normalize + pack (R6 layout) ----------------
__global__ void modulate_kernel(
    const float* __restrict__ w0, const float* __restrict__ w1,
    const float* __restrict__ w2, const float* __restrict__ w3,
    const float* __restrict__ w4,
    const float* __restrict__ m0, const float* __restrict__ m1,
    const float* __restrict__ m2, const float* __restrict__ m3,
    const float* __restrict__ m4)
{
    int gw   = (blockIdx.x * blockDim.x + threadIdx.x) >> 5;
    int lane = threadIdx.x & 31;
    if (gw >= BATCH * 514) return;
    int b = gw / 514;
    int r = gw % 514;
    int layer, o;
    if (r < 512) { layer = r >> 7; o = r & 127; }
    else         { layer = 4;      o = r - 512; }

    float* g = g_wmod + (size_t)b * WSTRIDE;

    if (layer < 4) {
        const float* w; const float* m; int fr, off, kpad;
        switch (layer) {
          case 0:  w = w0; m = m0; fr = 35;  off = OFFB0; kpad = 64;  break;
          case 1:  w = w1; m = m1; fr = 128; off = OFFB1; kpad = 128; break;
          case 2:  w = w2; m = m2; fr = 128; off = OFFB2; kpad = 128; break;
          default: w = w3; m = m3; fr = 128; off = OFFB3; kpad = 128; break;
        }
        float ss = 0.f;
        for (int k = lane; k < fr; k += 32) {
            float v = w[k * 128 + o] * m[((size_t)b * fr + k) * 128 + o];
            ss += v * v;
        }
        #pragma unroll
        for (int s = 16; s; s >>= 1) ss += __shfl_xor_sync(0xffffffffu, ss, s);
        float inv = 1.f / fmaxf(sqrtf(ss), 1e-12f);
        int sw = 4 * (o & 7);
        for (int k = lane; k < kpad; k += 32) {
            float v = 0.f;
            if (k < fr) v = w[k * 128 + o] * m[((size_t)b * fr + k) * 128 + o] * inv;
            g[off + o * kpad + (k ^ sw)] = __uint_as_float(f2tf32(v));
        }
        if (lane == 0) g[OFF_BIAS + layer * 128 + o] = w[fr * 128 + o];
    } else {
        float ss = 0.f;
        for (int k = lane; k < 128; k += 32) {
            float v = w4[k * 2 + o] * m4[((size_t)b * 128 + k) * 2 + o];
            ss += v * v;
        }
        #pragma unroll
        for (int s = 16; s; s >>= 1) ss += __shfl_xor_sync(0xffffffffu, ss, s);
        float inv = 1.f / fmaxf(sqrtf(ss), 1e-12f);
        for (int k = lane; k < 128; k += 32)
            g[OFF_W4 + k * 2 + o] = w4[k * 2 + o] * m4[((size_t)b * 128 + k) * 2 + o] * inv;
        if (lane == 0) g[OFF_W4 + 256 + o] = w4[128 * 2 + o];
    }
}

// ---------------- kernel B: tf32 mma.sync MLP, 64 px / 128 thr / 2 CTAs-per-SM ----------------
#define AP 132           // padded A row stride (floats)
#define MB_WF0    0
#define MB_WF1    8
#define MB_WREL0  16
#define MB_WREL1  24
#define BIAS_F    16     // float idx (byte 64), 770 floats (bias 512 + W4 258)
#define W4_F      528
#define A_B       4096   // 64*132*4 = 33792 -> ends 37888
#define WB0_B     38912  // 32KB
#define WB1_B     71680  // 32KB -> ends 104448
#define SMEM_BYTES 104448

// one n-half MMA pass: warp tile 32(m) x 32(n): mt=2, q=4  (R6 addressing)
template<int KSTEPS, int KP>
__device__ __forceinline__ void mma_half(
    const uint32_t* __restrict__ Asm, const uint32_t* __restrict__ Wsm,
    int mbase, int nbaseL, int lr, int lc, float (*acc)[4][4])
{
    const int s24 = (4 * lr) & 24;
    const int x0  = lc + ((4 * lr) & 4);
    const int x1  = x0 ^ 4;
    #pragma unroll
    for (int ks = 0; ks < KSTEPS; ks++) {
        const int kb  = ks * 8;
        const int kbs = kb ^ s24;
        uint32_t a[2][4];
        #pragma unroll
        for (int mt = 0; mt < 2; mt++) {
            int r0 = (mbase + mt * 16 + lr) * AP + kb + lc;
            a[mt][0] = Asm[r0];
            a[mt][1] = Asm[r0 + 8 * AP];
            a[mt][2] = Asm[r0 + 4];
            a[mt][3] = Asm[r0 + 8 * AP + 4];
        }
        #pragma unroll
        for (int q = 0; q < 4; q++) {
            int base = (nbaseL + q * 8 + lr) * KP + kbs;
            uint32_t b0 = Wsm[base + x0];
            uint32_t b1 = Wsm[base + x1];
            #pragma unroll
            for (int mt = 0; mt < 2; mt++) {
                asm volatile(
                    "mma.sync.aligned.m16n8k8.row.col.f32.tf32.tf32.f32 "
                    "{%0,%1,%2,%3}, {%4,%5,%6,%7}, {%8,%9}, {%0,%1,%2,%3};"
                    : "+f"(acc[mt][q][0]), "+f"(acc[mt][q][1]),
                      "+f"(acc[mt][q][2]), "+f"(acc[mt][q][3])
                    : "r"(a[mt][0]), "r"(a[mt][1]), "r"(a[mt][2]), "r"(a[mt][3]),
                      "r"(b0), "r"(b1));
            }
        }
    }
}

__global__ __launch_bounds__(128, 2)
void hyponet_kernel(const float* __restrict__ coord,
                    const float* __restrict__ lat,
                    float* __restrict__ out)
{
    extern __shared__ __align__(1024) char smem[];
    float*    smf = (float*)smem;
    uint32_t* Au  = (uint32_t*)(smem + A_B);
    float*    Af  = (float*)(smem + A_B);
    const uint32_t sb    = smem_to_u32(smem);
    const uint32_t wf0   = sb + MB_WF0,   wf1   = sb + MB_WF1;
    const uint32_t wrel0 = sb + MB_WREL0, wrel1 = sb + MB_WREL1;

    const int tid  = threadIdx.x;
    const int warp = tid >> 5, lane = tid & 31;
    const int lr = lane >> 2, lc = lane & 3;
    const int mbase  = (warp & 1) * 32;
    const int nbaseL = (warp >> 1) * 32;
    const int b     = blockIdx.x >> 10;           // 1024 CTAs per batch
    const int pbase = (blockIdx.x & 1023) << 6;   // *64
    const float* gw = g_wmod + (size_t)b * WSTRIDE;

    // weight halves: src float offset + byte count
    const int      hoff[8]   = {OFFB0, OFFB0 + 4096, OFFB1, OFFB1 + 8192,
                                OFFB2, OFFB2 + 8192, OFFB3, OFFB3 + 8192};
    const uint32_t hbytes[8] = {16384, 16384, 32768, 32768, 32768, 32768, 32768, 32768};

    if (tid == 0) {
        MBARRIER_INIT(wf0, 1);
        MBARRIER_INIT(wf1, 1);
        MBARRIER_INIT(wrel0, 4);
        MBARRIER_INIT(wrel1, 4);
    }
    __syncthreads();
    if (tid == 0) {
        MBARRIER_EXPECT_TX(wf0, hbytes[0]);
        BULK_G2S(sb + WB0_B, gw + hoff[0], hbytes[0], wf0);
        MBARRIER_EXPECT_TX(wf1, hbytes[1]);
        BULK_G2S(sb + WB1_B, gw + hoff[1], hbytes[1], wf1);
    }

    // ---- prologue ----
    if (tid < 64) {
        int p = tid, n = pbase + p;
        int y = n >> 8, x = n & 255;
        const float* c = coord + ((size_t)b * NPIX + n) * 3;
        float sy = (y + 0.5f) * 0.25f - 0.5f;
        float sx = (x + 0.5f) * 0.25f - 0.5f;
        float fy0 = floorf(sy), fx0 = floorf(sx);
        float fy = sy - fy0,    fx = sx - fx0;
        int y0 = max(0, min(LHW - 1, (int)fy0));
        int y1 = max(0, min(LHW - 1, (int)fy0 + 1));
        int x0 = max(0, min(LHW - 1, (int)fx0));
        int x1 = max(0, min(LHW - 1, (int)fx0 + 1));
        float w00 = (1.f - fy) * (1.f - fx), w01 = (1.f - fy) * fx;
        float w10 = fy * (1.f - fx),         w11 = fy * fx;
        const float* base = lat + (size_t)b * LHW * LHW * CLAT;
        const float4* q00 = (const float4*)(base + (y0 * LHW + x0) * CLAT);
        const float4* q01 = (const float4*)(base + (y0 * LHW + x1) * CLAT);
        const float4* q10 = (const float4*)(base + (y1 * LHW + x0) * CLAT);
        const float4* q11 = (const float4*)(base + (y1 * LHW + x1) * CLAT);
        uint32_t* arow = Au + p * AP;
        #pragma unroll
        for (int k = 0; k < 8; k++) {
            float4 a = q00[k], bb = q01[k], cc = q10[k], dd = q11[k];
            arow[4 * k + 0] = f2tf32(w00 * a.x + w01 * bb.x + w10 * cc.x + w11 * dd.x);
            arow[4 * k + 1] = f2tf32(w00 * a.y + w01 * bb.y + w10 * cc.y + w11 * dd.y);
            arow[4 * k + 2] = f2tf32(w00 * a.z + w01 * bb.z + w10 * cc.z + w11 * dd.z);
            arow[4 * k + 3] = f2tf32(w00 * a.w + w01 * bb.w + w10 * cc.w + w11 * dd.w);
        }
        arow[32] = f2tf32(c[0]);
        arow[33] = f2tf32(c[1]);
        arow[34] = f2tf32(c[2]);
        #pragma unroll
        for (int k = 35; k < 64; k++) arow[k] = 0;
    } else {
        for (int i = tid - 64; i < 770; i += 64) smf[BIAS_F + i] = gw[OFF_BIAS + i];
    }
    __syncthreads();

    #define LAYER_PASS(L, KS, KPV) do { \
        const int ph = (L) & 1; \
        float acc0[2][4][4] = {}; \
        float acc1[2][4][4] = {}; \
        MBARRIER_WAIT_PARITY(wf0, ph); \
        mma_half<KS, KPV>(Au, (const uint32_t*)(smem + WB0_B), mbase, nbaseL, lr, lc, acc0); \
        if (lane == 0) MBARRIER_ARRIVE(wrel0); \
        if (tid == 0 && (L) < 3) { \
            MBARRIER_WAIT_PARITY(wrel0, ph); \
            MBARRIER_EXPECT_TX(wf0, hbytes[2 * (L) + 2]); \
            BULK_G2S(sb + WB0_B, gw + hoff[2 * (L) + 2], hbytes[2 * (L) + 2], wf0); \
        } \
        MBARRIER_WAIT_PARITY(wf1, ph); \
        mma_half<KS, KPV>(Au, (const uint32_t*)(smem + WB1_B), mbase, nbaseL, lr, lc, acc1); \
        if (lane == 0) MBARRIER_ARRIVE(wrel1); \
        if (tid == 0 && (L) < 3) { \
            MBARRIER_WAIT_PARITY(wrel1, ph); \
            MBARRIER_EXPECT_TX(wf1, hbytes[2 * (L) + 3]); \
            BULK_G2S(sb + WB1_B, gw + hoff[2 * (L) + 3], hbytes[2 * (L) + 3], wf1); \
        } \
        __syncthreads(); \
        const float* biasL = smf + BIAS_F + (L) * 128; \
        _Pragma("unroll") \
        for (int h = 0; h < 2; h++) { \
            float (*acc)[4][4] = h ? acc1 : acc0; \
            _Pragma("unroll") \
            for (int mt = 0; mt < 2; mt++) { \
                _Pragma("unroll") \
                for (int q = 0; q < 4; q++) { \
                    int n0 = h * 64 + nbaseL + q * 8 + 2 * lc; \
                    float2 bv = *(const float2*)(biasL + n0); \
                    int r0 = mbase + mt * 16 + lr; \
                    uint2 v01, v23; \
                    v01.x = f2tf32(__sinf(acc[mt][q][0] + bv.x)); \
                    v01.y = f2tf32(__sinf(acc[mt][q][1] + bv.y)); \
                    v23.x = f2tf32(__sinf(acc[mt][q][2] + bv.x)); \
                    v23.y = f2tf32(__sinf(acc[mt][q][3] + bv.y)); \
                    *(uint2*)&Au[r0 * AP + n0]       = v01; \
                    *(uint2*)&Au[(r0 + 8) * AP + n0] = v23; \
                } \
            } \
        } \
        __syncthreads(); \
    } while (0)

    LAYER_PASS(0, 8, 64);
    LAYER_PASS(1, 16, 128);
    LAYER_PASS(2, 16, 128);
    LAYER_PASS(3, 16, 128);
    #undef LAYER_PASS

    // ---- final: 128 -> 2 dot + 0.5 (fp32) ----
    {
        const float* w4 = smf + W4_F;
        int o = tid >> 6, p = tid & 63;
        float acc = w4[256 + o];
        const float* arow = Af + p * AP;
        #pragma unroll 8
        for (int k = 0; k < 128; k += 4) {
            float4 a = *(const float4*)(arow + k);
            acc += a.x * w4[(k + 0) * 2 + o];
            acc += a.y * w4[(k + 1) * 2 + o];
            acc += a.z * w4[(k + 2) * 2 + o];
            acc += a.w * w4[(k + 3) * 2 + o];
        }
        out[((size_t)b * NPIX + pbase + p) * 2 + o] = acc + 0.5f;
    }
}

// ---------------- launch ----------------
extern "C" void kernel_launch(void* const* d_in, const int* in_sizes, int n_in,
                              void* d_out, int out_size)
{
    const float* coord = (const float*)d_in[0];
    const float* lat   = (const float*)d_in[1];

    modulate_kernel<<<(2056 * 32 + 255) / 256, 256>>>(
        (const float*)d_in[2], (const float*)d_in[3], (const float*)d_in[4],
        (const float*)d_in[5], (const float*)d_in[6],
        (const float*)d_in[7], (const float*)d_in[8], (const float*)d_in[9],
        (const float*)d_in[10], (const float*)d_in[11]);

    cudaFuncSetAttribute(hyponet_kernel,
                         cudaFuncAttributeMaxDynamicSharedMemorySize, SMEM_BYTES);
    hyponet_kernel<<<BATCH * (NPIX / 64), 128, SMEM_BYTES>>>(coord, lat, (float*)d_out);
}